// round 5
// baseline (speedup 1.0000x reference)
#include <cuda_runtime.h>
#include <math.h>

#define Bz 32
#define Lz 4096
#define Dz 1024
#define SPLITS 16
#define WARPS 8
#define ROWS_PER_WARP (Lz / SPLITS / WARPS)   // 32 == warp size (ballot)
#define NPART SPLITS                          // partials per batch
#define TOTAL_PART (Bz * NPART)

// Scratch (no cudaMalloc allowed). 2 MB partials + per-batch arrival counters.
__device__ float g_m[TOTAL_PART];
__device__ float g_s[TOTAL_PART];
__device__ float g_acc[TOTAL_PART][Dz];
__device__ unsigned g_cnt[Bz];                // zero-init; self-resets each launch

// ---------------------------------------------------------------------------
// Single fused kernel.
// Stage 1: warp online-softmax over 32 rows, software-pipelined: next row's
//          8x LDG.128 issued before current row's reduce/exp/update, so loads
//          stay in flight through the compute phase (2x MLP).
//          q lives in shared memory to free registers for the double buffer.
// Stage 2: CTA merge (8 warp states -> 1 partial) through shared memory.
// Stage 3: last CTA to finish a batch merges its 16 partials -> out[b,:].
// ---------------------------------------------------------------------------
__global__ void __launch_bounds__(256, 2)
tap_fused(const float* __restrict__ seq,
          const int* __restrict__ mask,       // bool marshalled as int32
          const float* __restrict__ query,
          float* __restrict__ out)
{
    const int b     = blockIdx.x / SPLITS;
    const int split = blockIdx.x % SPLITS;
    const int warp  = threadIdx.x >> 5;
    const int lane  = threadIdx.x & 31;
    const int t     = threadIdx.x;

    __shared__ float4 sq[Dz / 4];              // 4 KB query
    __shared__ float  sm_m[WARPS];
    __shared__ float  sm_s[WARPS];
    __shared__ float  sm_acc[WARPS][Dz];       // 32 KB
    __shared__ int    sm_last;

    sq[t] = reinterpret_cast<const float4*>(query)[t];
    __syncthreads();

    // ---------------- Stage 1: pipelined online softmax ----------------
    float m = -3.0e38f;
    float s = 0.0f;
    float4 acc[8];
#pragma unroll
    for (int ch = 0; ch < 8; ch++) acc[ch] = make_float4(0.f, 0.f, 0.f, 0.f);

    const int row0 = split * (Lz / SPLITS) + warp * ROWS_PER_WARP;
    const float* sb = seq + ((size_t)b * Lz + row0) * Dz;

    const int mv = mask[(size_t)b * Lz + row0 + lane];
    unsigned bits = __ballot_sync(0xffffffffu, mv != 0);

    float4 rc[8], rn[8];
    int i = -1;
    if (bits) {
        i = __ffs(bits) - 1;
        bits &= bits - 1;
        const float4* rp = reinterpret_cast<const float4*>(sb + (size_t)i * Dz);
#pragma unroll
        for (int ch = 0; ch < 8; ch++) rc[ch] = rp[ch * 32 + lane];
    }

    while (i >= 0) {
        // Prefetch next unmasked row (loads overlap the compute below)
        int j = -1;
        if (bits) {
            j = __ffs(bits) - 1;
            bits &= bits - 1;
            const float4* rp = reinterpret_cast<const float4*>(sb + (size_t)j * Dz);
#pragma unroll
            for (int ch = 0; ch < 8; ch++) rn[ch] = rp[ch * 32 + lane];
        }

        // Dot product with q (from smem)
        float dot = 0.f;
#pragma unroll
        for (int ch = 0; ch < 8; ch++) {
            const float4 qv = sq[ch * 32 + lane];
            dot += rc[ch].x * qv.x + rc[ch].y * qv.y
                 + rc[ch].z * qv.z + rc[ch].w * qv.w;
        }
#pragma unroll
        for (int o = 16; o > 0; o >>= 1)
            dot += __shfl_xor_sync(0xffffffffu, dot, o);
        dot *= 0.03125f;                       // 1/sqrt(1024)

        // Online softmax update
        const float mnew = fmaxf(m, dot);
        const float corr = __expf(m - mnew);
        const float w    = __expf(dot - mnew);
        s = s * corr + w;
#pragma unroll
        for (int ch = 0; ch < 8; ch++) {
            acc[ch].x = acc[ch].x * corr + w * rc[ch].x;
            acc[ch].y = acc[ch].y * corr + w * rc[ch].y;
            acc[ch].z = acc[ch].z * corr + w * rc[ch].z;
            acc[ch].w = acc[ch].w * corr + w * rc[ch].w;
        }
        m = mnew;

#pragma unroll
        for (int ch = 0; ch < 8; ch++) rc[ch] = rn[ch];
        i = j;
    }

    // ---------------- Stage 2: CTA merge -> one partial ----------------
    if (lane == 0) { sm_m[warp] = m; sm_s[warp] = s; }
    float4* wp = reinterpret_cast<float4*>(sm_acc[warp]);
#pragma unroll
    for (int ch = 0; ch < 8; ch++) wp[ch * 32 + lane] = acc[ch];
    __syncthreads();

    float M = -3.0e38f;
#pragma unroll
    for (int w = 0; w < WARPS; w++) M = fmaxf(M, sm_m[w]);
    float e[WARPS];
    float S = 0.f;
#pragma unroll
    for (int w = 0; w < WARPS; w++) {
        e[w] = __expf(sm_m[w] - M);
        S += e[w] * sm_s[w];
    }

    const int p = b * NPART + split;
    float4 o4 = make_float4(0.f, 0.f, 0.f, 0.f);
#pragma unroll
    for (int w = 0; w < WARPS; w++) {
        const float4 a = reinterpret_cast<const float4*>(sm_acc[w])[t];
        o4.x += e[w] * a.x; o4.y += e[w] * a.y;
        o4.z += e[w] * a.z; o4.w += e[w] * a.w;
    }
    reinterpret_cast<float4*>(g_acc[p])[t] = o4;
    if (t == 0) { g_m[p] = M; g_s[p] = S; }

    // ---------------- Stage 3: last CTA of batch merges ----------------
    __threadfence();
    if (t == 0) {
        const unsigned done = atomicAdd(&g_cnt[b], 1u);
        sm_last = (done == NPART - 1);
        if (sm_last) g_cnt[b] = 0;             // reset for next graph replay
    }
    __syncthreads();
    if (!sm_last) return;

    // Reuse sm_m/sm_s storage for the 16 batch partials (16 <= Dz sizes ok)
    __shared__ float pm[NPART], ps[NPART];
    if (t < NPART) {
        pm[t] = g_m[b * NPART + t];
        ps[t] = g_s[b * NPART + t];
    }
    __syncthreads();

    float M2 = -3.0e38f;
#pragma unroll
    for (int k = 0; k < NPART; k++) M2 = fmaxf(M2, pm[k]);
    float e2[NPART];
    float S2 = 0.f;
#pragma unroll
    for (int k = 0; k < NPART; k++) {
        e2[k] = __expf(pm[k] - M2);
        S2 += e2[k] * ps[k];
    }
    const float invS = 1.0f / S2;

    float4 r4 = make_float4(0.f, 0.f, 0.f, 0.f);
#pragma unroll
    for (int k = 0; k < NPART; k++) {
        const float4 a =
            reinterpret_cast<const float4*>(g_acc[b * NPART + k])[t];
        r4.x += e2[k] * a.x; r4.y += e2[k] * a.y;
        r4.z += e2[k] * a.z; r4.w += e2[k] * a.w;
    }
    r4.x *= invS; r4.y *= invS; r4.z *= invS; r4.w *= invS;
    reinterpret_cast<float4*>(out)[b * (Dz / 4) + t] = r4;
}

// ---------------------------------------------------------------------------
extern "C" void kernel_launch(void* const* d_in, const int* in_sizes, int n_in,
                              void* d_out, int out_size)
{
    const float* seq   = (const float*)d_in[0];
    const int*   mask  = (const int*)d_in[1];
    const float* query = (const float*)d_in[2];
    float*       out   = (float*)d_out;

    tap_fused<<<Bz * SPLITS, 256>>>(seq, mask, query, out);
}